// round 4
// baseline (speedup 1.0000x reference)
#include <cuda_runtime.h>
#include <math.h>
#include <stdint.h>

// ---------------------------------------------------------------------------
// Problem dimensions (fixed by the reference)
// ---------------------------------------------------------------------------
#define B_ENC   8
#define BEAM    4
#define NH      16
#define S_ENC   4096
#define S_DEC   1020
#define QT      4
#define HD      64
#define HID     1024
#define NB      32        // B_ENC * BEAM
#define NROWS   128       // NB * QT
#define S_DEC_T 1024      // S_DEC + QT
#define KV_TOT  5120      // S_ENC + S_DEC_T

// Scratch for projected q, k, v  (layout: [row = b*4+t][HID = h*64+d])
__device__ float g_q[NROWS * HID];
__device__ float g_k[NROWS * HID];
__device__ float g_v[NROWS * HID];

// ---------------------------------------------------------------------------
// cp.async helpers
// ---------------------------------------------------------------------------
__device__ __forceinline__ void cp_async16(void* smem, const void* gmem) {
    uint32_t s = (uint32_t)__cvta_generic_to_shared(smem);
    asm volatile("cp.async.cg.shared.global [%0], [%1], 16;\n" :: "r"(s), "l"(gmem));
}
__device__ __forceinline__ void cp_commit() {
    asm volatile("cp.async.commit_group;\n");
}
template<int N> __device__ __forceinline__ void cp_wait() {
    asm volatile("cp.async.wait_group %0;\n" :: "n"(N));
}

// ---------------------------------------------------------------------------
// Projection kernel:  out[m][n] = sum_k hidden[m][k] * W[n][k] + b[n]
// Tile 16(m) x 64(n), K-chunks of 64, double buffered. grid (16, 8, 3), 128 thr.
// Per thread: 4m x 2n register block (n strided by 32 for conflict-free LDS).
// ---------------------------------------------------------------------------
#define PJ_TM 16
#define PJ_TN 64
#define PJ_TK 64
#define PJ_AS 68   // padded row stride (floats)

__global__ void __launch_bounds__(128) proj_kernel(
    const float* __restrict__ hidden,
    const float* __restrict__ Wq, const float* __restrict__ bq,
    const float* __restrict__ Wk, const float* __restrict__ bk,
    const float* __restrict__ Wv, const float* __restrict__ bv)
{
    extern __shared__ float psm[];
    float* A  = psm;                          // [2][16][68]
    float* Bt = psm + 2 * PJ_TM * PJ_AS;      // [2][64][68]

    const float* W; const float* bias; float* out;
    int z = blockIdx.z;
    if (z == 0)      { W = Wq; bias = bq; out = g_q; }
    else if (z == 1) { W = Wk; bias = bk; out = g_k; }
    else             { W = Wv; bias = bv; out = g_v; }

    const int m0  = blockIdx.y * PJ_TM;
    const int n0  = blockIdx.x * PJ_TN;
    const int tid = threadIdx.x;

    const int nb = tid & 31;   // n in {nb, nb+32}
    const int mb = tid >> 5;   // 0..3 -> rows mb*4 .. mb*4+3

    float acc[4][2];
#pragma unroll
    for (int i = 0; i < 4; i++) { acc[i][0] = 0.f; acc[i][1] = 0.f; }

    // ---- loaders (A: 16x64 = 256 f4 -> 2/thr, B: 64x64 = 1024 f4 -> 8/thr)
    auto loadA = [&](int kc, int buf) {
        const float* src = hidden + m0 * HID + kc * PJ_TK;
        float* dst = A + buf * PJ_TM * PJ_AS;
#pragma unroll
        for (int i = 0; i < 2; i++) {
            int f = i * 128 + tid; int r = f >> 4, c4 = f & 15;
            cp_async16(dst + r * PJ_AS + c4 * 4, src + r * HID + c4 * 4);
        }
    };
    auto loadB = [&](int kc, int buf) {
        const float* src = W + n0 * HID + kc * PJ_TK;
        float* dst = Bt + buf * PJ_TN * PJ_AS;
#pragma unroll
        for (int i = 0; i < 8; i++) {
            int f = i * 128 + tid; int r = f >> 4, c4 = f & 15;
            cp_async16(dst + r * PJ_AS + c4 * 4, src + r * HID + c4 * 4);
        }
    };

    loadA(0, 0); loadB(0, 0); cp_commit();

    for (int kc = 0; kc < 16; kc++) {
        int cur = kc & 1, nxt = cur ^ 1;
        if (kc + 1 < 16) { loadA(kc + 1, nxt); loadB(kc + 1, nxt); cp_commit(); cp_wait<1>(); }
        else             { cp_wait<0>(); }
        __syncthreads();

        const float* Ab = A  + cur * PJ_TM * PJ_AS;
        const float* Bb = Bt + cur * PJ_TN * PJ_AS;
#pragma unroll
        for (int k4 = 0; k4 < 16; k4++) {
            float4 a[4], b[2];
#pragma unroll
            for (int i = 0; i < 4; i++)
                a[i] = *(const float4*)(Ab + (mb * 4 + i) * PJ_AS + k4 * 4);
#pragma unroll
            for (int j = 0; j < 2; j++)
                b[j] = *(const float4*)(Bb + (nb + 32 * j) * PJ_AS + k4 * 4);
#pragma unroll
            for (int i = 0; i < 4; i++)
#pragma unroll
                for (int j = 0; j < 2; j++)
                    acc[i][j] += a[i].x * b[j].x + a[i].y * b[j].y
                               + a[i].z * b[j].z + a[i].w * b[j].w;
        }
        __syncthreads();
    }

#pragma unroll
    for (int j = 0; j < 2; j++) {
        int n = n0 + nb + 32 * j;
        float bias_n = __ldg(bias + n);
#pragma unroll
        for (int i = 0; i < 4; i++) {
            int m = m0 + mb * 4 + i;
            out[m * HID + n] = acc[i][j] + bias_n;
        }
    }
}

// ---------------------------------------------------------------------------
// Attention kernel: one CTA per (b_enc, h). Streams 4096 shared enc keys for
// all 4 beams (16 queries), then each beam's 1024 dec keys (incl. 4 new
// tokens from g_k / g_v). Flash-style online softmax, O in registers.
// ---------------------------------------------------------------------------
#define TT 128          // keys per tile
#define AT_THREADS 256

struct AttnSmem {
    float K[2][TT][68];
    float V[2][TT][68];
    float S[16][132];
    float Qs[16][68];
    float m[16];
    float l[16];
    float alpha[16];
};

__global__ void __launch_bounds__(AT_THREADS, 1) attn_kernel(
    const float* __restrict__ mask,
    const float* __restrict__ encK, const float* __restrict__ encV,
    const float* __restrict__ decK, const float* __restrict__ decV,
    float* __restrict__ out)
{
    extern __shared__ char smraw[];
    AttnSmem& sm = *reinterpret_cast<AttnSmem*>(smraw);

    const int tid  = threadIdx.x;
    const int cta  = blockIdx.x;
    const int benc = cta >> 4;
    const int h    = cta & 15;

    // ---- load queries (16 rows x 64), pre-scaled by 1/sqrt(D)
    for (int f = tid; f < 16 * 16; f += AT_THREADS) {
        int r = f >> 4, c4 = f & 15;
        float4 q = *(const float4*)(g_q + (benc * 16 + r) * HID + h * 64 + c4 * 4);
        q.x *= 0.125f; q.y *= 0.125f; q.z *= 0.125f; q.w *= 0.125f;
        *(float4*)(&sm.Qs[r][c4 * 4]) = q;
    }
    if (tid < 16) { sm.m[tid] = -INFINITY; sm.l[tid] = 0.f; }

    // ---- context-accumulator ownership (fixed for the whole kernel)
    const int ks = tid >> 6;          // key segment 0..3 (32 keys each)
    const int rr = tid & 63;
    const int qb = rr >> 4;           // query block 0..3 (4 queries each)
    const int db = rr & 15;           // d block (4 floats each)
    float Oacc[4][4];
#pragma unroll
    for (int i = 0; i < 4; i++)
#pragma unroll
        for (int j = 0; j < 4; j++) Oacc[i][j] = 0.f;

    // ---- tile loader: tiles 0..31 = enc, 32..63 = dec (8 per beam)
    auto issue_tile = [&](int ti, int buf) {
        if (ti < 32) {
            const float* kb = encK + ((size_t)(benc * 16 + h) * S_ENC + ti * TT) * HD;
            const float* vb = encV + ((size_t)(benc * 16 + h) * S_ENC + ti * TT) * HD;
#pragma unroll
            for (int i = 0; i < 8; i++) {
                int f = i * AT_THREADS + tid; int r = f >> 4, c4 = f & 15;
                cp_async16(&sm.K[buf][r][c4 * 4], kb + r * HD + c4 * 4);
                cp_async16(&sm.V[buf][r][c4 * 4], vb + r * HD + c4 * 4);
            }
        } else {
            int j = ti - 32; int beam = j >> 3; int tb = (j & 7) * TT;
            int b = benc * 4 + beam;
#pragma unroll
            for (int i = 0; i < 8; i++) {
                int f = i * AT_THREADS + tid; int r = f >> 4, c4 = f & 15;
                int s = tb + r;
                const float* ksrc; const float* vsrc;
                if (s < S_DEC) {
                    size_t base = ((size_t)(b * 16 + h) * S_DEC + s) * HD + c4 * 4;
                    ksrc = decK + base; vsrc = decV + base;
                } else {
                    size_t base = (size_t)(b * 4 + (s - S_DEC)) * HID + h * 64 + c4 * 4;
                    ksrc = g_k + base; vsrc = g_v + base;
                }
                cp_async16(&sm.K[buf][r][c4 * 4], ksrc);
                cp_async16(&sm.V[buf][r][c4 * 4], vsrc);
            }
        }
    };

    issue_tile(0, 0); cp_commit();

    for (int ti = 0; ti < 64; ti++) {
        const int cur = ti & 1, nxt = cur ^ 1;
        if (ti + 1 < 64) { issue_tile(ti + 1, nxt); cp_commit(); cp_wait<1>(); }
        else             { cp_wait<0>(); }
        __syncthreads();

        // ================= phase 1: scores (+mask) into sm.S =================
        if (ti < 32) {
            // 16 queries x 128 keys; thread: 4q x 2k (keys kt, kt+64)
            const int sqb = tid >> 6;
            const int kt  = tid & 63;
            float acc[4][2];
#pragma unroll
            for (int i = 0; i < 4; i++) { acc[i][0] = 0.f; acc[i][1] = 0.f; }
#pragma unroll
            for (int d4 = 0; d4 < 16; d4++) {
                float4 k0 = *(const float4*)(&sm.K[cur][kt][d4 * 4]);
                float4 k1 = *(const float4*)(&sm.K[cur][kt + 64][d4 * 4]);
#pragma unroll
                for (int i = 0; i < 4; i++) {
                    float4 q = *(const float4*)(&sm.Qs[sqb * 4 + i][d4 * 4]);
                    acc[i][0] += q.x * k0.x + q.y * k0.y + q.z * k0.z + q.w * k0.w;
                    acc[i][1] += q.x * k1.x + q.y * k1.y + q.z * k1.z + q.w * k1.w;
                }
            }
            const int sb = ti * TT;
#pragma unroll
            for (int i = 0; i < 4; i++) {
                int qi = sqb * 4 + i;             // qi = beam*4 + t
                int b  = benc * 4 + sqb;          // beam == sqb
                const float* mrow = mask + (size_t)(b * 4 + i) * KV_TOT + sb;
                sm.S[qi][kt]      = acc[i][0] + __ldg(mrow + kt);
                sm.S[qi][kt + 64] = acc[i][1] + __ldg(mrow + kt + 64);
            }
        } else {
            // dec: 4 active queries x 128 keys; thread: 2q x 1k
            int j = ti - 32; int beam = j >> 3; int tb = (j & 7) * TT;
            const int qh = tid >> 7;   // 0,1
            const int kt = tid & 127;
            float acc[2] = {0.f, 0.f};
#pragma unroll
            for (int d4 = 0; d4 < 16; d4++) {
                float4 kv = *(const float4*)(&sm.K[cur][kt][d4 * 4]);
#pragma unroll
                for (int i = 0; i < 2; i++) {
                    float4 q = *(const float4*)(&sm.Qs[beam * 4 + qh * 2 + i][d4 * 4]);
                    acc[i] += q.x * kv.x + q.y * kv.y + q.z * kv.z + q.w * kv.w;
                }
            }
            int b = benc * 4 + beam;
#pragma unroll
            for (int i = 0; i < 2; i++) {
                int t = qh * 2 + i;
                sm.S[beam * 4 + t][kt] =
                    acc[i] + __ldg(mask + (size_t)(b * 4 + t) * KV_TOT + S_ENC + tb + kt);
            }
        }
        __syncthreads();

        // ================= phase 2: online softmax update =================
        {
            const int w  = tid >> 5;
            const int ln = tid & 31;
            const int qlo = (ti < 32) ? 0  : ((ti - 32) >> 3) * 4;
            const int qhi = (ti < 32) ? 16 : qlo + 4;
#pragma unroll
            for (int qq = 0; qq < 2; qq++) {
                int q = w * 2 + qq;
                if (q >= qlo && q < qhi) {
                    float v0 = sm.S[q][ln],      v1 = sm.S[q][ln + 32];
                    float v2 = sm.S[q][ln + 64], v3 = sm.S[q][ln + 96];
                    float mx = fmaxf(fmaxf(v0, v1), fmaxf(v2, v3));
#pragma unroll
                    for (int o = 16; o > 0; o >>= 1)
                        mx = fmaxf(mx, __shfl_xor_sync(0xffffffffu, mx, o));
                    float mold  = sm.m[q];
                    float mnew  = fmaxf(mold, mx);
                    float msafe = (mnew == -INFINITY) ? 0.f : mnew;
                    float al    = __expf(mold - msafe);
                    float p0 = __expf(v0 - msafe), p1 = __expf(v1 - msafe);
                    float p2 = __expf(v2 - msafe), p3 = __expf(v3 - msafe);
                    sm.S[q][ln]      = p0; sm.S[q][ln + 32] = p1;
                    sm.S[q][ln + 64] = p2; sm.S[q][ln + 96] = p3;
                    float s = p0 + p1 + p2 + p3;
#pragma unroll
                    for (int o = 16; o > 0; o >>= 1)
                        s += __shfl_xor_sync(0xffffffffu, s, o);
                    if (ln == 0) {
                        sm.m[q] = mnew;
                        sm.l[q] = sm.l[q] * al + s;
                        sm.alpha[q] = al;
                    }
                } else {
                    if (ln == 0) sm.alpha[q] = 1.f;
                }
            }
        }
        __syncthreads();

        // ================= phase 3: context accumulate =================
        {
            float a4[4];
#pragma unroll
            for (int i = 0; i < 4; i++) a4[i] = sm.alpha[qb * 4 + i];
#pragma unroll
            for (int i = 0; i < 4; i++)
#pragma unroll
                for (int j = 0; j < 4; j++) Oacc[i][j] *= a4[i];

            bool do_ctx = (ti < 32) || (qb == ((ti - 32) >> 3));
            if (do_ctx) {
#pragma unroll
                for (int sc = 0; sc < 8; sc++) {
                    int s0 = ks * 32 + sc * 4;
                    float pr[4][4];
#pragma unroll
                    for (int i = 0; i < 4; i++) {
                        float4 p = *(const float4*)(&sm.S[qb * 4 + i][s0]);
                        pr[i][0] = p.x; pr[i][1] = p.y; pr[i][2] = p.z; pr[i][3] = p.w;
                    }
#pragma unroll
                    for (int u = 0; u < 4; u++) {
                        float4 vv = *(const float4*)(&sm.V[cur][s0 + u][db * 4]);
#pragma unroll
                        for (int i = 0; i < 4; i++) {
                            Oacc[i][0] += pr[i][u] * vv.x;
                            Oacc[i][1] += pr[i][u] * vv.y;
                            Oacc[i][2] += pr[i][u] * vv.z;
                            Oacc[i][3] += pr[i][u] * vv.w;
                        }
                    }
                }
            }
        }
        __syncthreads();   // protect buffers before next prefetch overwrites
    }

    // ---- reduce the 4 key-segment partials, normalize, write out ----------
    float* Ored = &sm.K[0][0][0];          // reuse: [4][16][64]
#pragma unroll
    for (int i = 0; i < 4; i++)
#pragma unroll
        for (int j = 0; j < 4; j++)
            Ored[(ks * 16 + qb * 4 + i) * 64 + db * 4 + j] = Oacc[i][j];
    __syncthreads();

#pragma unroll
    for (int i = 0; i < 4; i++) {
        int f  = i * AT_THREADS + tid;
        int qi = f >> 6, d = f & 63;
        float sum = Ored[(0 * 16 + qi) * 64 + d] + Ored[(1 * 16 + qi) * 64 + d]
                  + Ored[(2 * 16 + qi) * 64 + d] + Ored[(3 * 16 + qi) * 64 + d];
        out[(size_t)(benc * 16 + qi) * HID + h * 64 + d] = sum / sm.l[qi];
    }
}

// ---------------------------------------------------------------------------
// Launch
// ---------------------------------------------------------------------------
extern "C" void kernel_launch(void* const* d_in, const int* in_sizes, int n_in,
                              void* d_out, int out_size)
{
    const float* hidden = (const float*)d_in[0];
    const float* mask   = (const float*)d_in[1];
    const float* encK   = (const float*)d_in[2];
    const float* encV   = (const float*)d_in[3];
    const float* decK   = (const float*)d_in[4];
    const float* decV   = (const float*)d_in[5];
    const float* Wq     = (const float*)d_in[6];
    const float* bq     = (const float*)d_in[7];
    const float* Wk     = (const float*)d_in[8];
    const float* bk     = (const float*)d_in[9];
    const float* Wv     = (const float*)d_in[10];
    const float* bv     = (const float*)d_in[11];
    float* out = (float*)d_out;

    const int pj_smem = (2 * PJ_TM * PJ_AS + 2 * PJ_TN * PJ_AS) * (int)sizeof(float);
    cudaFuncSetAttribute(proj_kernel, cudaFuncAttributeMaxDynamicSharedMemorySize, pj_smem);
    cudaFuncSetAttribute(attn_kernel, cudaFuncAttributeMaxDynamicSharedMemorySize,
                         (int)sizeof(AttnSmem));

    dim3 pg(HID / PJ_TN, NROWS / PJ_TM, 3);     // (16, 8, 3)
    proj_kernel<<<pg, 128, pj_smem>>>(hidden, Wq, bq, Wk, bk, Wv, bv);

    attn_kernel<<<B_ENC * NH, AT_THREADS, sizeof(AttnSmem)>>>(
        mask, encK, encV, decK, decV, out);
}

// round 7
// speedup vs baseline: 1.0318x; 1.0318x over previous
#include <cuda_runtime.h>
#include <math.h>
#include <stdint.h>

// ---------------------------------------------------------------------------
// Problem dimensions
// ---------------------------------------------------------------------------
#define B_ENC   8
#define NH      16
#define S_ENC   4096
#define S_DEC   1020
#define QT      4
#define HD      64
#define HID     1024
#define NROWS   128       // 32 rows * 4 tokens
#define KV_TOT  5120

// Scratch: projected q/k/v, and split-KV partials
__device__ __align__(16) float g_q[NROWS * HID];
__device__ __align__(16) float g_k[NROWS * HID];
__device__ __align__(16) float g_v[NROWS * HID];
// partials: [chunk 4][pair 128][q 16][68]  (O[64], m@64, l@65)
#define CH_STRIDE (128 * 16 * 68)
__device__ __align__(16) float g_part[4 * CH_STRIDE];

// ---------------------------------------------------------------------------
// helpers
// ---------------------------------------------------------------------------
__device__ __forceinline__ void cp_async16(void* smem, const void* gmem) {
    uint32_t s = (uint32_t)__cvta_generic_to_shared(smem);
    asm volatile("cp.async.cg.shared.global [%0], [%1], 16;\n" :: "r"(s), "l"(gmem));
}
__device__ __forceinline__ void cp_commit() {
    asm volatile("cp.async.commit_group;\n");
}
template<int N> __device__ __forceinline__ void cp_wait() {
    asm volatile("cp.async.wait_group %0;\n" :: "n"(N));
}

typedef unsigned long long ull;
__device__ __forceinline__ void ffma2(ull& d, ull a, ull b) {
    asm("fma.rn.f32x2 %0, %1, %2, %0;" : "+l"(d) : "l"(a), "l"(b));
}
__device__ __forceinline__ void fmul2(ull& d, ull a) {
    asm("mul.rn.f32x2 %0, %0, %1;" : "+l"(d) : "l"(a));
}
__device__ __forceinline__ ull pack2(float x, float y) {
    ull r; asm("mov.b64 %0, {%1, %2};" : "=l"(r) : "f"(x), "f"(y)); return r;
}
__device__ __forceinline__ float2 unpack2(ull v) {
    float2 f; asm("mov.b64 {%0, %1}, %2;" : "=f"(f.x), "=f"(f.y) : "l"(v)); return f;
}

// ---------------------------------------------------------------------------
// Projection kernel (unchanged from passing R4 kernel)
// ---------------------------------------------------------------------------
#define PJ_TM 16
#define PJ_TN 64
#define PJ_TK 64
#define PJ_AS 68

__global__ void __launch_bounds__(128) proj_kernel(
    const float* __restrict__ hidden,
    const float* __restrict__ Wq, const float* __restrict__ bq,
    const float* __restrict__ Wk, const float* __restrict__ bk,
    const float* __restrict__ Wv, const float* __restrict__ bv)
{
    extern __shared__ float psm[];
    float* A  = psm;
    float* Bt = psm + 2 * PJ_TM * PJ_AS;

    const float* W; const float* bias; float* out;
    int z = blockIdx.z;
    if (z == 0)      { W = Wq; bias = bq; out = g_q; }
    else if (z == 1) { W = Wk; bias = bk; out = g_k; }
    else             { W = Wv; bias = bv; out = g_v; }

    const int m0  = blockIdx.y * PJ_TM;
    const int n0  = blockIdx.x * PJ_TN;
    const int tid = threadIdx.x;
    const int nb = tid & 31;
    const int mb = tid >> 5;

    float acc[4][2];
#pragma unroll
    for (int i = 0; i < 4; i++) { acc[i][0] = 0.f; acc[i][1] = 0.f; }

    auto loadA = [&](int kc, int buf) {
        const float* src = hidden + m0 * HID + kc * PJ_TK;
        float* dst = A + buf * PJ_TM * PJ_AS;
#pragma unroll
        for (int i = 0; i < 2; i++) {
            int f = i * 128 + tid; int r = f >> 4, c4 = f & 15;
            cp_async16(dst + r * PJ_AS + c4 * 4, src + r * HID + c4 * 4);
        }
    };
    auto loadB = [&](int kc, int buf) {
        const float* src = W + n0 * HID + kc * PJ_TK;
        float* dst = Bt + buf * PJ_TN * PJ_AS;
#pragma unroll
        for (int i = 0; i < 8; i++) {
            int f = i * 128 + tid; int r = f >> 4, c4 = f & 15;
            cp_async16(dst + r * PJ_AS + c4 * 4, src + r * HID + c4 * 4);
        }
    };

    loadA(0, 0); loadB(0, 0); cp_commit();

    for (int kc = 0; kc < 16; kc++) {
        int cur = kc & 1, nxt = cur ^ 1;
        if (kc + 1 < 16) { loadA(kc + 1, nxt); loadB(kc + 1, nxt); cp_commit(); cp_wait<1>(); }
        else             { cp_wait<0>(); }
        __syncthreads();

        const float* Ab = A  + cur * PJ_TM * PJ_AS;
        const float* Bb = Bt + cur * PJ_TN * PJ_AS;
#pragma unroll
        for (int k4 = 0; k4 < 16; k4++) {
            float4 a[4], b[2];
#pragma unroll
            for (int i = 0; i < 4; i++)
                a[i] = *(const float4*)(Ab + (mb * 4 + i) * PJ_AS + k4 * 4);
#pragma unroll
            for (int j = 0; j < 2; j++)
                b[j] = *(const float4*)(Bb + (nb + 32 * j) * PJ_AS + k4 * 4);
#pragma unroll
            for (int i = 0; i < 4; i++)
#pragma unroll
                for (int j = 0; j < 2; j++)
                    acc[i][j] += a[i].x * b[j].x + a[i].y * b[j].y
                               + a[i].z * b[j].z + a[i].w * b[j].w;
        }
        __syncthreads();
    }

#pragma unroll
    for (int j = 0; j < 2; j++) {
        int n = n0 + nb + 32 * j;
        float bias_n = __ldg(bias + n);
#pragma unroll
        for (int i = 0; i < 4; i++) {
            int m = m0 + mb * 4 + i;
            out[m * HID + n] = acc[i][j] + bias_n;
        }
    }
}

// ---------------------------------------------------------------------------
// Attention: split-KV. grid = 512 = 4 chunks x (8 benc x 16 h).
//   chunk 0: enc keys [0,2048)   chunk 1: enc keys [2048,4096)
//   chunk 2: dec beams {0,1}     chunk 3: dec beams {2,3}
// 32 tiles of 64 keys per chunk. 2 CTAs/SM, f32x2 math, flash softmax.
// ---------------------------------------------------------------------------
#define TT 64
#define NTILE 32

struct AttnSmem {
    float K[2][TT][68];
    float V[2][TT][68];
    float S4[4][16][68];    // d-split score partials
    float P_T[TT][20];      // probs transposed [key][q]
    float Qs[16][68];
    float m[16], l[16], alpha[16];
};

__global__ void __launch_bounds__(256, 2) attn_kernel(
    const float* __restrict__ mask,
    const float* __restrict__ encK, const float* __restrict__ encV,
    const float* __restrict__ decK, const float* __restrict__ decV)
{
    extern __shared__ char smraw[];
    AttnSmem& sm = *reinterpret_cast<AttnSmem*>(smraw);

    const int tid   = threadIdx.x;
    const int bid   = blockIdx.x;
    const int chunk = bid & 3;
    const int pair  = bid >> 2;          // benc*16 + h
    const int benc  = pair >> 4;
    const int h     = pair & 15;

    // ---- load queries (16 rows x 64), pre-scaled
    {
        int r = tid >> 4, c4 = tid & 15;
        float4 q = *(const float4*)(g_q + (size_t)(benc * 16 + r) * HID + h * 64 + c4 * 4);
        q.x *= 0.125f; q.y *= 0.125f; q.z *= 0.125f; q.w *= 0.125f;
        *(float4*)(&sm.Qs[r][c4 * 4]) = q;
    }
    if (tid < 16) { sm.m[tid] = -INFINITY; sm.l[tid] = 0.f; }

    // ---- phase-index decompositions
    const int ds  = tid >> 6;            // P1 d-split 0..3
    const int r1  = tid & 63;
    const int qb1 = r1 >> 4;             // P1 q-block (enc) / query idx (dec)
    const int kb  = r1 & 15;             // P1 key base (keys kb+16u)
    const int p_qb = tid & 3;            // P3 q-block
    const int p_db = (tid >> 2) & 7;     // P3 d-block (8 floats)
    const int p_ks = tid >> 5;           // P3 key segment (8 keys)

    ull Oacc[4][4];                      // [q][d-pair-of-2] over 8 d floats
#pragma unroll
    for (int i = 0; i < 4; i++)
#pragma unroll
        for (int j = 0; j < 4; j++) Oacc[i][j] = 0ull;

    // ---- tile loader
    auto issue_tile = [&](int ti, int buf) {
        if (chunk < 2) {
            int key0 = chunk * 2048 + ti * 64;
            const float* kbase = encK + ((size_t)(benc * 16 + h) * S_ENC + key0) * HD;
            const float* vbase = encV + ((size_t)(benc * 16 + h) * S_ENC + key0) * HD;
#pragma unroll
            for (int i = 0; i < 4; i++) {
                int f = i * 256 + tid; int r = f >> 4, c4 = f & 15;
                cp_async16(&sm.K[buf][r][c4 * 4], kbase + r * HD + c4 * 4);
                cp_async16(&sm.V[buf][r][c4 * 4], vbase + r * HD + c4 * 4);
            }
        } else {
            int beam = (chunk - 2) * 2 + (ti >> 4);
            int tib  = ti & 15;
            int b    = benc * 4 + beam;
#pragma unroll
            for (int i = 0; i < 4; i++) {
                int f = i * 256 + tid; int r = f >> 4, c4 = f & 15;
                int s = tib * 64 + r;
                const float* ksrc; const float* vsrc;
                if (s < S_DEC) {
                    size_t base = ((size_t)(b * 16 + h) * S_DEC + s) * HD + c4 * 4;
                    ksrc = decK + base; vsrc = decV + base;
                } else {
                    size_t base = (size_t)(b * 4 + (s - S_DEC)) * HID + h * 64 + c4 * 4;
                    ksrc = g_k + base; vsrc = g_v + base;
                }
                cp_async16(&sm.K[buf][r][c4 * 4], ksrc);
                cp_async16(&sm.V[buf][r][c4 * 4], vsrc);
            }
        }
    };

    issue_tile(0, 0); cp_commit();

    for (int ti = 0; ti < NTILE; ti++) {
        const int cur = ti & 1, nxt = cur ^ 1;
        if (ti + 1 < NTILE) { issue_tile(ti + 1, nxt); cp_commit(); cp_wait<1>(); }
        else                { cp_wait<0>(); }
        __syncthreads();

        const int beam = (chunk < 2) ? -1 : (chunk - 2) * 2 + (ti >> 4);

        // ============ phase 1: d-split partial scores into S4 ============
        if (chunk < 2) {
            ull acc2[4][4];
#pragma unroll
            for (int i = 0; i < 4; i++)
#pragma unroll
                for (int u = 0; u < 4; u++) acc2[i][u] = 0ull;
#pragma unroll
            for (int dd = 0; dd < 4; dd++) {
                int d4 = (ds * 4 + dd) * 4;
                ull k2[4][2];
#pragma unroll
                for (int u = 0; u < 4; u++) {
                    float4 kf = *(const float4*)(&sm.K[cur][kb + 16 * u][d4]);
                    k2[u][0] = pack2(kf.x, kf.y);
                    k2[u][1] = pack2(kf.z, kf.w);
                }
#pragma unroll
                for (int i = 0; i < 4; i++) {
                    ull qa = *(const ull*)(&sm.Qs[qb1 * 4 + i][d4]);
                    ull qc = *(const ull*)(&sm.Qs[qb1 * 4 + i][d4 + 2]);
#pragma unroll
                    for (int u = 0; u < 4; u++) {
                        ffma2(acc2[i][u], qa, k2[u][0]);
                        ffma2(acc2[i][u], qc, k2[u][1]);
                    }
                }
            }
#pragma unroll
            for (int i = 0; i < 4; i++)
#pragma unroll
                for (int u = 0; u < 4; u++) {
                    float2 t = unpack2(acc2[i][u]);
                    sm.S4[ds][qb1 * 4 + i][kb + 16 * u] = t.x + t.y;
                }
        } else {
            // dec: 4 active queries, thread = 1 query x 4 keys
            ull acc2[4];
#pragma unroll
            for (int u = 0; u < 4; u++) acc2[u] = 0ull;
            int qrow = beam * 4 + qb1;
#pragma unroll
            for (int dd = 0; dd < 4; dd++) {
                int d4 = (ds * 4 + dd) * 4;
                ull qa = *(const ull*)(&sm.Qs[qrow][d4]);
                ull qc = *(const ull*)(&sm.Qs[qrow][d4 + 2]);
#pragma unroll
                for (int u = 0; u < 4; u++) {
                    float4 kf = *(const float4*)(&sm.K[cur][kb + 16 * u][d4]);
                    ffma2(acc2[u], qa, pack2(kf.x, kf.y));
                    ffma2(acc2[u], qc, pack2(kf.z, kf.w));
                }
            }
#pragma unroll
            for (int u = 0; u < 4; u++) {
                float2 t = unpack2(acc2[u]);
                sm.S4[ds][qrow][kb + 16 * u] = t.x + t.y;
            }
        }
        __syncthreads();

        // ============ phase 2: sum partials + mask, online softmax ========
        {
            const int w  = tid >> 5;
            const int ln = tid & 31;
            int qlo, qhi, kcol0;
            if (chunk < 2) { qlo = 0; qhi = 16; kcol0 = chunk * 2048 + ti * 64; }
            else           { qlo = beam * 4; qhi = qlo + 4; kcol0 = S_ENC + (ti & 15) * 64; }
#pragma unroll
            for (int qq = 0; qq < 2; qq++) {
                int q = w * 2 + qq;
                if (q >= qlo && q < qhi) {
                    int b4t = (benc * 4 + (q >> 2)) * 4 + (q & 3);
                    const float* mrow = mask + (size_t)b4t * KV_TOT + kcol0;
                    float s0 = sm.S4[0][q][ln]      + sm.S4[1][q][ln]
                             + sm.S4[2][q][ln]      + sm.S4[3][q][ln]      + __ldg(mrow + ln);
                    float s1 = sm.S4[0][q][ln + 32] + sm.S4[1][q][ln + 32]
                             + sm.S4[2][q][ln + 32] + sm.S4[3][q][ln + 32] + __ldg(mrow + ln + 32);
                    float mx = fmaxf(s0, s1);
#pragma unroll
                    for (int o = 16; o > 0; o >>= 1)
                        mx = fmaxf(mx, __shfl_xor_sync(0xffffffffu, mx, o));
                    float mold  = sm.m[q];
                    float mnew  = fmaxf(mold, mx);
                    float al    = __expf(mold - mnew);
                    float p0 = __expf(s0 - mnew), p1 = __expf(s1 - mnew);
                    sm.P_T[ln][q]      = p0;
                    sm.P_T[ln + 32][q] = p1;
                    float s = p0 + p1;
#pragma unroll
                    for (int o = 16; o > 0; o >>= 1)
                        s += __shfl_xor_sync(0xffffffffu, s, o);
                    if (ln == 0) {
                        sm.m[q] = mnew;
                        sm.l[q] = sm.l[q] * al + s;
                        sm.alpha[q] = al;
                    }
                } else if (ln == 0) {
                    sm.alpha[q] = 1.f;
                }
            }
        }
        __syncthreads();

        // ============ phase 3: context accumulate (f32x2) ================
        {
#pragma unroll
            for (int i = 0; i < 4; i++) {
                float a = sm.alpha[p_qb * 4 + i];
                ull aa = pack2(a, a);
#pragma unroll
                for (int j = 0; j < 4; j++) fmul2(Oacc[i][j], aa);
            }
            bool do_ctx = (chunk < 2) || (p_qb == beam);
            if (do_ctx) {
#pragma unroll
                for (int kk = 0; kk < 8; kk++) {
                    int key = p_ks * 8 + kk;
                    float4 pr = *(const float4*)(&sm.P_T[key][p_qb * 4]);
                    ull pp[4] = { pack2(pr.x, pr.x), pack2(pr.y, pr.y),
                                  pack2(pr.z, pr.z), pack2(pr.w, pr.w) };
                    ull vv[4];
#pragma unroll
                    for (int j = 0; j < 4; j++)
                        vv[j] = *(const ull*)(&sm.V[cur][key][p_db * 8 + 2 * j]);
#pragma unroll
                    for (int i = 0; i < 4; i++)
#pragma unroll
                        for (int j = 0; j < 4; j++)
                            ffma2(Oacc[i][j], pp[i], vv[j]);
                }
            }
        }
        __syncthreads();
    }

    // ---- reduce 8 key-segment partials, write chunk partial to gmem -------
    float* Ored = &sm.K[0][0][0];        // reuse: [8][16][64] = 8192 floats
#pragma unroll
    for (int i = 0; i < 4; i++) {
        int q = p_qb * 4 + i;
#pragma unroll
        for (int j = 0; j < 4; j++)
            *(ull*)(&Ored[(p_ks * 16 + q) * 64 + p_db * 8 + 2 * j]) = Oacc[i][j];
    }
    __syncthreads();

    float* gp = g_part + (size_t)chunk * CH_STRIDE + (size_t)pair * 16 * 68;
#pragma unroll
    for (int i = 0; i < 4; i++) {
        int f = i * 256 + tid;
        int qi = f >> 6, d = f & 63;
        float s = 0.f;
#pragma unroll
        for (int seg = 0; seg < 8; seg++)
            s += Ored[(seg * 16 + qi) * 64 + d];
        gp[qi * 68 + d] = s;
    }
    if (tid < 16) {
        gp[tid * 68 + 64] = sm.m[tid];
        gp[tid * 68 + 65] = sm.l[tid];
    }
}

// ---------------------------------------------------------------------------
// Merge the 4 chunk partials. grid 128, block 256 (thread = (q, 4d)).
// ---------------------------------------------------------------------------
__global__ void __launch_bounds__(256) reduce_kernel(float* __restrict__ out)
{
    const int pair = blockIdx.x;
    const int tid  = threadIdx.x;
    const int q    = tid >> 4;
    const int d4   = (tid & 15) * 4;
    const float* gp = g_part + (size_t)pair * 16 * 68;

    float m[4], l[4];
#pragma unroll
    for (int c = 0; c < 4; c++) {
        m[c] = gp[(size_t)c * CH_STRIDE + q * 68 + 64];
        l[c] = gp[(size_t)c * CH_STRIDE + q * 68 + 65];
    }
    float ms = fmaxf(fmaxf(m[0], m[1]), fmaxf(m[2], m[3]));
    float4 acc = make_float4(0.f, 0.f, 0.f, 0.f);
    float lsum = 0.f;
#pragma unroll
    for (int c = 0; c < 4; c++) {
        float wgt = __expf(m[c] - ms);
        lsum += wgt * l[c];
        float4 o = *(const float4*)(gp + (size_t)c * CH_STRIDE + q * 68 + d4);
        acc.x += wgt * o.x; acc.y += wgt * o.y;
        acc.z += wgt * o.z; acc.w += wgt * o.w;
    }
    float inv = 1.f / lsum;
    acc.x *= inv; acc.y *= inv; acc.z *= inv; acc.w *= inv;
    int benc = pair >> 4, h = pair & 15;
    *(float4*)(out + (size_t)(benc * 16 + q) * HID + h * 64 + d4) = acc;
}

// ---------------------------------------------------------------------------
// Launch
// ---------------------------------------------------------------------------
extern "C" void kernel_launch(void* const* d_in, const int* in_sizes, int n_in,
                              void* d_out, int out_size)
{
    const float* hidden = (const float*)d_in[0];
    const float* mask   = (const float*)d_in[1];
    const float* encK   = (const float*)d_in[2];
    const float* encV   = (const float*)d_in[3];
    const float* decK   = (const float*)d_in[4];
    const float* decV   = (const float*)d_in[5];
    const float* Wq     = (const float*)d_in[6];
    const float* bq     = (const float*)d_in[7];
    const float* Wk     = (const float*)d_in[8];
    const float* bk     = (const float*)d_in[9];
    const float* Wv     = (const float*)d_in[10];
    const float* bv     = (const float*)d_in[11];
    float* out = (float*)d_out;

    const int pj_smem = (2 * PJ_TM * PJ_AS + 2 * PJ_TN * PJ_AS) * (int)sizeof(float);
    cudaFuncSetAttribute(proj_kernel, cudaFuncAttributeMaxDynamicSharedMemorySize, pj_smem);
    cudaFuncSetAttribute(attn_kernel, cudaFuncAttributeMaxDynamicSharedMemorySize,
                         (int)sizeof(AttnSmem));

    dim3 pg(HID / PJ_TN, NROWS / PJ_TM, 3);
    proj_kernel<<<pg, 128, pj_smem>>>(hidden, Wq, bq, Wk, bk, Wv, bv);

    attn_kernel<<<512, 256, sizeof(AttnSmem)>>>(mask, encK, encV, decK, decV);

    reduce_kernel<<<128, 256>>>(out);
}